// round 10
// baseline (speedup 1.0000x reference)
#include <cuda_runtime.h>
#include <math.h>
#include <stdint.h>

#define H 1024
#define V 50257
#define L 128
#define NB 592                  // 148 SMs x 4 resident
#define TB 16384u               // tile: 4 rows x 1024 floats

// ---- persistent scratch ----
__device__ __align__(16) float g_attn_scratch[L];
__device__ __align__(16) float g_attn_applied[H];
__device__ __align__(16) float g_x[H];
__device__ __align__(16) float g_h[H];
__device__ __align__(16) float g_gates[4 * H];   // preset with biases by k_comb
__device__ __align__(16) float g_bmax[NB];
__device__ __align__(16) float g_bsum[NB];
__device__ float    g_logZ;
__device__ unsigned g_ctr_attn = 0, g_ctr_gate = 0, g_ctr_out = 0, g_done = 0;
__device__ unsigned g_flag_z = 0;

__device__ __forceinline__ float warp_sum(float v) {
    #pragma unroll
    for (int o = 16; o; o >>= 1) v += __shfl_down_sync(0xffffffffu, v, o);
    return v;
}
__device__ __forceinline__ float warp_max(float v) {
    #pragma unroll
    for (int o = 16; o; o >>= 1) v = fmaxf(v, __shfl_down_sync(0xffffffffu, v, o));
    return v;
}
__device__ __forceinline__ float dot4(float4 a, float4 b) {
    return a.x * b.x + a.y * b.y + a.z * b.z + a.w * b.w;
}
__device__ __forceinline__ uint64_t mkpolicy() {
    uint64_t p;
    asm("createpolicy.fractional.L2::evict_first.b64 %0, 1.0;" : "=l"(p));
    return p;
}
__device__ __forceinline__ void bulk_cp(void* dst_smem, const void* src,
                                        unsigned bytes, unsigned mbar, uint64_t pol) {
    unsigned d = (unsigned)__cvta_generic_to_shared(dst_smem);
    asm volatile(
        "cp.async.bulk.shared::cluster.global.mbarrier::complete_tx::bytes.L2::cache_hint"
        " [%0], [%1], %2, [%3], %4;"
        :: "r"(d), "l"(src), "r"(bytes), "r"(mbar), "l"(pol) : "memory");
}
__device__ __forceinline__ void mbar_init(unsigned mbar, unsigned cnt) {
    asm volatile("mbarrier.init.shared.b64 [%0], %1;" :: "r"(mbar), "r"(cnt) : "memory");
}
__device__ __forceinline__ void mbar_expect(unsigned mbar, unsigned bytes) {
    asm volatile("mbarrier.arrive.expect_tx.shared.b64 _, [%0], %1;"
                 :: "r"(mbar), "r"(bytes) : "memory");
}
__device__ __forceinline__ void mbar_wait(unsigned mbar, unsigned parity) {
    asm volatile(
        "{\n\t.reg .pred P;\n\t"
        "W_%=:\n\t"
        "mbarrier.try_wait.parity.acquire.cta.shared::cta.b64 P, [%0], %1, 0x989680;\n\t"
        "@P bra.uni D_%=;\n\t"
        "bra.uni W_%=;\n\t"
        "D_%=:\n\t}"
        :: "r"(mbar), "r"(parity) : "memory");
}
__device__ __forceinline__ unsigned smem_u32(const void* p) {
    return (unsigned)__cvta_generic_to_shared(p);
}

// ---------------------------------------------------------------------------
// attn logits (block per row) + fused softmax in last arriving block
// ---------------------------------------------------------------------------
__global__ void k_attn(const int* __restrict__ tokens,
                       const float* __restrict__ emb,
                       const float* __restrict__ h0,
                       const float* __restrict__ attn_W,
                       const float* __restrict__ attn_b,
                       float* __restrict__ attn_w_out) {
    int l = blockIdx.x;
    const float4* erow = (const float4*)(emb + (size_t)tokens[0] * H);
    const float4* hrow = (const float4*)h0;
    const float4* w    = (const float4*)(attn_W + (size_t)l * 2 * H);
    float acc = 0.f;
    for (int i = threadIdx.x; i < 2 * H / 4; i += blockDim.x) {
        float4 wv = __ldcs(w + i);
        float4 xv = (i < H / 4) ? erow[i] : hrow[i - H / 4];
        acc += dot4(wv, xv);
    }
    __shared__ float s[8];
    acc = warp_sum(acc);
    if ((threadIdx.x & 31) == 0) s[threadIdx.x >> 5] = acc;
    __syncthreads();
    __shared__ unsigned is_last;
    if (threadIdx.x == 0) {
        float v = 0.f;
        #pragma unroll
        for (int k = 0; k < 8; k++) v += s[k];
        g_attn_scratch[l] = v + attn_b[l];
        __threadfence();
        is_last = (atomicAdd(&g_ctr_attn, 1u) == L - 1);
    }
    __syncthreads();
    if (!is_last) return;

    __threadfence();
    __shared__ float sm[L];
    int t = threadIdx.x;
    float v = 0.f;
    if (t < L) { v = g_attn_scratch[t]; sm[t] = v; }
    __syncthreads();
    if (t < L) {
        for (int st = 64; st; st >>= 1) { if (t < st) sm[t] = fmaxf(sm[t], sm[t + st]); __syncthreads(); }
    } else { for (int st = 64; st; st >>= 1) __syncthreads(); }
    float m = sm[0]; __syncthreads();
    float e = (t < L) ? expf(v - m) : 0.f;
    if (t < L) sm[t] = e;
    __syncthreads();
    if (t < L) {
        for (int st = 64; st; st >>= 1) { if (t < st) sm[t] += sm[t + st]; __syncthreads(); }
    } else { for (int st = 64; st; st >>= 1) __syncthreads(); }
    if (t < L) {
        float wgt = e / sm[0];
        attn_w_out[t]     = wgt;
        g_attn_scratch[t] = wgt;
    }
    if (t == 0) g_ctr_attn = 0;
}

// ---------------------------------------------------------------------------
// attn_applied[j] = sum_l w[l] * enc[l][j]
// ---------------------------------------------------------------------------
__global__ void k_attn_applied(const float* __restrict__ enc) {
    int t  = threadIdx.x;
    int jl = t & 31, lg = t >> 5;
    int j  = blockIdx.x * 32 + jl;
    float acc = 0.f;
    #pragma unroll
    for (int k = 0; k < 16; k++) {
        int l = lg * 16 + k;
        acc += g_attn_scratch[l] * enc[l * H + j];
    }
    __shared__ float s[8][32];
    s[lg][jl] = acc;
    __syncthreads();
    if (lg == 0) {
        float v = acc;
        #pragma unroll
        for (int k = 1; k < 8; k++) v += s[k][jl];
        g_attn_applied[j] = v;
    }
}

// ---------------------------------------------------------------------------
// x = relu(comb_W @ [embedded||attn_applied] + comb_b) + gate bias preset
// ---------------------------------------------------------------------------
__global__ void k_comb(const int* __restrict__ tokens,
                       const float* __restrict__ emb,
                       const float* __restrict__ comb_W,
                       const float* __restrict__ comb_b,
                       const float* __restrict__ b_ih,
                       const float* __restrict__ b_hh) {
    if (threadIdx.x < 32) {
        int gi = blockIdx.x * 32 + threadIdx.x;
        g_gates[gi] = b_ih[gi] + b_hh[gi];
    }
    int warp = threadIdx.x >> 5, lane = threadIdx.x & 31;
    int row = blockIdx.x * 8 + warp;
    const float4* erow = (const float4*)(emb + (size_t)tokens[0] * H);
    const float4* arow = (const float4*)g_attn_applied;
    const float4* w    = (const float4*)(comb_W + (size_t)row * 2 * H);
    float4 wr[16];
    #pragma unroll
    for (int k = 0; k < 16; k++) wr[k] = __ldcs(w + lane + 32 * k);
    float acc = 0.f;
    #pragma unroll
    for (int k = 0; k < 16; k++) {
        int i = lane + 32 * k;
        float4 xv = (i < 256) ? erow[i] : arow[i - 256];
        acc += dot4(wr[k], xv);
    }
    acc = warp_sum(acc);
    if (lane == 0) g_x[row] = fmaxf(acc + comb_b[row], 0.f);
}

// ---------------------------------------------------------------------------
// k_gates: persistent 592 blocks, 3-4 tiles each, double-buffered bulk copies.
// Tiles 0..1023 = W_ih (vs x); 1024..2047 = W_hh (vs h0). The block counting
// the 2048th tile runs the LSTM pointwise inline (fused k_lstm_pw).
// ---------------------------------------------------------------------------
__global__ void __launch_bounds__(128) k_gates(const float* __restrict__ W_ih,
                                               const float* __restrict__ W_hh,
                                               const float* __restrict__ h0,
                                               const float* __restrict__ c0,
                                               float* __restrict__ h_out,
                                               float* __restrict__ c_out) {
    __shared__ __align__(128) float4 buf[2][1024];   // 32KB
    __shared__ float4 svx[256], svh[256];
    __shared__ uint64_t mbar[2];
    __shared__ unsigned s_last;
    int tid = threadIdx.x, warp = tid >> 5, lane = tid & 31;
    int b = blockIdx.x;
    uint64_t pol = mkpolicy();
    unsigned mb[2] = { smem_u32(&mbar[0]), smem_u32(&mbar[1]) };

    if (tid == 0) { mbar_init(mb[0], 1); mbar_init(mb[1], 1); }
    svx[tid]       = ((const float4*)g_x)[tid];
    svx[tid + 128] = ((const float4*)g_x)[tid + 128];
    svh[tid]       = ((const float4*)h0)[tid];
    svh[tid + 128] = ((const float4*)h0)[tid + 128];
    __syncthreads();

    int nt = (2048 - b + NB - 1) / NB;               // 4 for b<272, else 3
    if (tid == 0) {
        int t0 = b;
        const float* s0 = (t0 < 1024) ? W_ih + (size_t)t0 * 4 * H
                                      : W_hh + (size_t)(t0 - 1024) * 4 * H;
        mbar_expect(mb[0], TB); bulk_cp(buf[0], s0, TB, mb[0], pol);
        if (nt > 1) {
            int t1 = b + NB;
            const float* s1 = (t1 < 1024) ? W_ih + (size_t)t1 * 4 * H
                                          : W_hh + (size_t)(t1 - 1024) * 4 * H;
            mbar_expect(mb[1], TB); bulk_cp(buf[1], s1, TB, mb[1], pol);
        }
    }

    for (int k = 0; k < nt; k++) {
        int s = k & 1;
        mbar_wait(mb[s], (k >> 1) & 1);
        int t = b + NB * k;
        const float4* vec = (t < 1024) ? svx : svh;
        float a = 0.f;
        #pragma unroll
        for (int kk = 0; kk < 8; kk++)
            a += dot4(buf[s][warp * 256 + lane + 32 * kk], vec[lane + 32 * kk]);
        a = warp_sum(a);
        if (lane == 0) atomicAdd(&g_gates[(4 * t + warp) & 4095], a);
        __threadfence();
        __syncthreads();
        if (tid == 0) {
            s_last = (atomicAdd(&g_ctr_gate, 1u) == 2047u);
            if (k + 2 < nt) {
                int tn = b + NB * (k + 2);
                const float* sn = (tn < 1024) ? W_ih + (size_t)tn * 4 * H
                                              : W_hh + (size_t)(tn - 1024) * 4 * H;
                mbar_expect(mb[s], TB); bulk_cp(buf[s], sn, TB, mb[s], pol);
            }
        }
        __syncthreads();
        if (s_last) {
            // all 2048 tiles accumulated -> LSTM pointwise (fused)
            __threadfence();
            for (int u = tid; u < H; u += 128) {
                float gi = g_gates[u], gf = g_gates[H + u];
                float gg = g_gates[2 * H + u], go = g_gates[3 * H + u];
                float ig = 1.f / (1.f + expf(-gi));
                float fg = 1.f / (1.f + expf(-gf));
                float gt = tanhf(gg);
                float og = 1.f / (1.f + expf(-go));
                float cn = fg * c0[u] + ig * gt;
                float hn = og * tanhf(cn);
                c_out[u] = cn; h_out[u] = hn; g_h[u] = hn;
            }
            if (tid == 0) g_ctr_gate = 0u;
        }
    }
}

// ---------------------------------------------------------------------------
// output projection: persistent 592 blocks, 3-stage bulk-copy pipeline (48KB
// dynamic smem), online logsumexp, fused logZ + final subtract (flag sync).
// ---------------------------------------------------------------------------
__global__ void __launch_bounds__(128, 4) k_out(const float* __restrict__ out_W,
                                                const float* __restrict__ out_b,
                                                float* __restrict__ out) {
    extern __shared__ __align__(128) char dsm[];
    float4*   buf  = (float4*)dsm;                         // 3 x 1024 float4 = 48KB
    float4*   sh4  = (float4*)(dsm + 3 * 16384);           // 256 float4 = 4KB
    uint64_t* mbarp = (uint64_t*)(dsm + 3 * 16384 + 4096); // 3 barriers
    __shared__ float    s_red[8];
    __shared__ unsigned s_last;

    int tid = threadIdx.x, warp = tid >> 5, lane = tid & 31;
    int b = blockIdx.x;
    uint64_t pol = mkpolicy();
    unsigned mb[3] = { smem_u32(mbarp), smem_u32(mbarp + 1), smem_u32(mbarp + 2) };

    if (tid == 0) { mbar_init(mb[0], 1); mbar_init(mb[1], 1); mbar_init(mb[2], 1); }
    sh4[tid]       = ((const float4*)g_h)[tid];
    sh4[tid + 128] = ((const float4*)g_h)[tid + 128];
    __syncthreads();

    const int nt = 21 + (b < 132);                   // 12564 full 4-row tiles
    if (tid == 0) {
        #pragma unroll
        for (int k = 0; k < 3; k++) {
            mbar_expect(mb[k], TB);
            bulk_cp(buf + k * 1024, out_W + ((size_t)b + (size_t)NB * k) * 4 * H, TB, mb[k], pol);
        }
    }

    float m = -INFINITY, ss = 0.f;
    int s = 0;
    for (int k = 0; k < nt; k++) {
        mbar_wait(mb[s], (k / 3) & 1);
        size_t row = ((size_t)b + (size_t)NB * k) * 4 + warp;
        float a = 0.f;
        #pragma unroll
        for (int kk = 0; kk < 8; kk++)
            a += dot4(buf[s * 1024 + warp * 256 + lane + 32 * kk], sh4[lane + 32 * kk]);
        a = warp_sum(a);
        if (lane == 0) {
            float lg = a + out_b[row];
            out[row] = lg;
            if (lg > m) { ss = ss * expf(m - lg) + 1.f; m = lg; }
            else        { ss += expf(lg - m); }
        }
        __syncthreads();                               // all reads of stage s done
        if (tid == 0 && k + 3 < nt) {
            mbar_expect(mb[s], TB);
            bulk_cp(buf + s * 1024, out_W + ((size_t)b + (size_t)NB * (k + 3)) * 4 * H, TB, mb[s], pol);
        }
        s = (s == 2) ? 0 : s + 1;
    }

    // tail row 50256 (block 0, warp 0)
    if (b == 0 && warp == 0) {
        const float4* w = (const float4*)(out_W + (size_t)50256 * H);
        float a = 0.f;
        #pragma unroll
        for (int kk = 0; kk < 8; kk++) a += dot4(__ldcs(w + lane + 32 * kk), sh4[lane + 32 * kk]);
        a = warp_sum(a);
        if (lane == 0) {
            float lg = a + out_b[50256];
            out[50256] = lg;
            if (lg > m) { ss = ss * expf(m - lg) + 1.f; m = lg; }
            else        { ss += expf(lg - m); }
        }
    }

    // per-block (max,sum) -> last block reduces logZ -> flag
    if (lane == 0) { s_red[warp] = m; s_red[4 + warp] = ss; }
    __syncthreads();
    if (tid == 0) {
        float M = fmaxf(fmaxf(s_red[0], s_red[1]), fmaxf(s_red[2], s_red[3]));
        float S = 0.f;
        #pragma unroll
        for (int k = 0; k < 4; k++) S += s_red[4 + k] * expf(s_red[k] - M);
        g_bmax[b] = M; g_bsum[b] = S;
        __threadfence();
        s_last = (atomicAdd(&g_ctr_out, 1u) == NB - 1);
    }
    __syncthreads();
    if (s_last) {
        __threadfence();
        float mm = -INFINITY;
        for (int k = tid; k < NB; k += 128) mm = fmaxf(mm, g_bmax[k]);
        mm = warp_max(mm);
        if (lane == 0) s_red[warp] = mm;
        __syncthreads();
        if (tid == 0) s_red[0] = fmaxf(fmaxf(s_red[0], s_red[1]), fmaxf(s_red[2], s_red[3]));
        __syncthreads();
        float M = s_red[0];
        __syncthreads();
        float S = 0.f;
        for (int k = tid; k < NB; k += 128) S += g_bsum[k] * expf(g_bmax[k] - M);
        S = warp_sum(S);
        if (lane == 0) s_red[4 + warp] = S;
        __syncthreads();
        if (tid == 0) {
            g_logZ = M + logf(s_red[4] + s_red[5] + s_red[6] + s_red[7]);
            g_ctr_out = 0u;
            __threadfence();
            atomicExch(&g_flag_z, 1u);
        }
    }

    // fused final subtract: every block handles its own rows
    if (tid == 0) { while (*(volatile unsigned*)&g_flag_z == 0u) __nanosleep(64); }
    __syncthreads(); __threadfence();
    float lz = g_logZ;
    for (int i = tid; i < nt * 4; i += 128) {
        size_t row = ((size_t)b + (size_t)NB * (i >> 2)) * 4 + (i & 3);
        out[row] -= lz;
    }
    if (b == 0 && tid == 0) out[50256] -= lz;
    __threadfence(); __syncthreads();
    if (tid == 0) {
        if (atomicAdd(&g_done, 1u) == NB - 1) { g_done = 0u; __threadfence(); atomicExch(&g_flag_z, 0u); }
    }
}

extern "C" void kernel_launch(void* const* d_in, const int* in_sizes, int n_in,
                              void* d_out, int out_size) {
    const int*   tokens = (const int*)  d_in[0];
    const float* h0     = (const float*)d_in[1];
    const float* c0     = (const float*)d_in[2];
    const float* enc    = (const float*)d_in[3];
    const float* emb    = (const float*)d_in[4];
    const float* attn_W = (const float*)d_in[5];
    const float* attn_b = (const float*)d_in[6];
    const float* comb_W = (const float*)d_in[7];
    const float* comb_b = (const float*)d_in[8];
    const float* W_ih   = (const float*)d_in[9];
    const float* W_hh   = (const float*)d_in[10];
    const float* b_ih   = (const float*)d_in[11];
    const float* b_hh   = (const float*)d_in[12];
    const float* out_W  = (const float*)d_in[13];
    const float* out_b  = (const float*)d_in[14];

    float* out    = (float*)d_out;          // [V] log-probs
    float* h_out  = out + V;                // [H]
    float* c_out  = out + V + H;            // [H]
    float* aw_out = out + V + 2 * H;        // [L]

    static int smem_set = 0;
    const int OUT_SMEM = 3 * 16384 + 4096 + 32;
    if (!smem_set) {
        cudaFuncSetAttribute(k_out, cudaFuncAttributeMaxDynamicSharedMemorySize, OUT_SMEM);
        smem_set = 1;
    }

    k_attn        <<<L, 256>>>(tokens, emb, h0, attn_W, attn_b, aw_out);
    k_attn_applied<<<H / 32, 256>>>(enc);
    k_comb        <<<H / 8, 256>>>(tokens, emb, comb_W, comb_b, b_ih, b_hh);
    k_gates       <<<NB, 128>>>(W_ih, W_hh, h0, c0, h_out, c_out);
    k_out         <<<NB, 128, OUT_SMEM>>>(out_W, out_b, out);
}

// round 11
// speedup vs baseline: 1.0498x; 1.0498x over previous
#include <cuda_runtime.h>
#include <math.h>
#include <stdint.h>

#define H 1024
#define V 50257
#define L 128
#define NB 592                  // 148 SMs x 4 resident
#define TB 16384u               // tile: 4 rows x 1024 floats

// ---- persistent scratch ----
__device__ __align__(16) float g_attn_scratch[L];
__device__ __align__(16) float g_attn_applied[H];
__device__ __align__(16) float g_x[H];
__device__ __align__(16) float g_h[H];
__device__ __align__(16) float g_gates[4 * H];
__device__ __align__(16) float g_bmax[NB];
__device__ __align__(16) float g_bsum[NB];
__device__ float    g_logZ;
__device__ unsigned g_ctr_attn = 0, g_ctr_ih = 0, g_ctr_out = 0, g_done = 0;
__device__ unsigned g_flag_z = 0;

__device__ __forceinline__ float warp_sum(float v) {
    #pragma unroll
    for (int o = 16; o; o >>= 1) v += __shfl_down_sync(0xffffffffu, v, o);
    return v;
}
__device__ __forceinline__ float warp_max(float v) {
    #pragma unroll
    for (int o = 16; o; o >>= 1) v = fmaxf(v, __shfl_down_sync(0xffffffffu, v, o));
    return v;
}
__device__ __forceinline__ float dot4(float4 a, float4 b) {
    return a.x * b.x + a.y * b.y + a.z * b.z + a.w * b.w;
}
__device__ __forceinline__ uint64_t mkpolicy() {
    uint64_t p;
    asm("createpolicy.fractional.L2::evict_first.b64 %0, 1.0;" : "=l"(p));
    return p;
}
__device__ __forceinline__ void bulk_cp(void* dst_smem, const void* src,
                                        unsigned bytes, unsigned mbar, uint64_t pol) {
    unsigned d = (unsigned)__cvta_generic_to_shared(dst_smem);
    asm volatile(
        "cp.async.bulk.shared::cluster.global.mbarrier::complete_tx::bytes.L2::cache_hint"
        " [%0], [%1], %2, [%3], %4;"
        :: "r"(d), "l"(src), "r"(bytes), "r"(mbar), "l"(pol) : "memory");
}
__device__ __forceinline__ void mbar_init(unsigned mbar, unsigned cnt) {
    asm volatile("mbarrier.init.shared.b64 [%0], %1;" :: "r"(mbar), "r"(cnt) : "memory");
}
__device__ __forceinline__ void mbar_expect(unsigned mbar, unsigned bytes) {
    asm volatile("mbarrier.arrive.expect_tx.shared.b64 _, [%0], %1;"
                 :: "r"(mbar), "r"(bytes) : "memory");
}
__device__ __forceinline__ void mbar_wait(unsigned mbar, unsigned parity) {
    asm volatile(
        "{\n\t.reg .pred P;\n\t"
        "W_%=:\n\t"
        "mbarrier.try_wait.parity.acquire.cta.shared::cta.b64 P, [%0], %1, 0x989680;\n\t"
        "@P bra.uni D_%=;\n\t"
        "bra.uni W_%=;\n\t"
        "D_%=:\n\t}"
        :: "r"(mbar), "r"(parity) : "memory");
}
__device__ __forceinline__ unsigned smem_u32(const void* p) {
    return (unsigned)__cvta_generic_to_shared(p);
}

// ---------------------------------------------------------------------------
// k_hh (side stream): g_gates[r] = W_hh[r]·h0 + b_ih[r] + b_hh[r]
// 1024 blocks x 128 thr, warp per gate row, loads staged in registers.
// ---------------------------------------------------------------------------
__global__ void __launch_bounds__(128) k_hh(const float* __restrict__ W_hh,
                                            const float* __restrict__ h0,
                                            const float* __restrict__ b_ih,
                                            const float* __restrict__ b_hh) {
    int tid = threadIdx.x, warp = tid >> 5, lane = tid & 31;
    int r = blockIdx.x * 4 + warp;
    const float4* w = (const float4*)(W_hh + (size_t)r * H);
    float4 vr[8];
    #pragma unroll
    for (int k = 0; k < 8; k++) vr[k] = __ldcs(w + lane + 32 * k);
    __shared__ float4 sh[256];
    sh[tid]       = ((const float4*)h0)[tid];
    sh[tid + 128] = ((const float4*)h0)[tid + 128];
    __syncthreads();
    float a = 0.f;
    #pragma unroll
    for (int k = 0; k < 8; k++) a += dot4(vr[k], sh[lane + 32 * k]);
    a = warp_sum(a);
    if (lane == 0) g_gates[r] = a + b_ih[r] + b_hh[r];
}

// ---------------------------------------------------------------------------
// attn logits (block per row) + fused softmax in last arriving block
// ---------------------------------------------------------------------------
__global__ void k_attn(const int* __restrict__ tokens,
                       const float* __restrict__ emb,
                       const float* __restrict__ h0,
                       const float* __restrict__ attn_W,
                       const float* __restrict__ attn_b,
                       float* __restrict__ attn_w_out) {
    int l = blockIdx.x;
    const float4* erow = (const float4*)(emb + (size_t)tokens[0] * H);
    const float4* hrow = (const float4*)h0;
    const float4* w    = (const float4*)(attn_W + (size_t)l * 2 * H);
    float acc = 0.f;
    for (int i = threadIdx.x; i < 2 * H / 4; i += blockDim.x) {
        float4 wv = __ldcs(w + i);
        float4 xv = (i < H / 4) ? erow[i] : hrow[i - H / 4];
        acc += dot4(wv, xv);
    }
    __shared__ float s[8];
    acc = warp_sum(acc);
    if ((threadIdx.x & 31) == 0) s[threadIdx.x >> 5] = acc;
    __syncthreads();
    __shared__ unsigned is_last;
    if (threadIdx.x == 0) {
        float v = 0.f;
        #pragma unroll
        for (int k = 0; k < 8; k++) v += s[k];
        g_attn_scratch[l] = v + attn_b[l];
        __threadfence();
        is_last = (atomicAdd(&g_ctr_attn, 1u) == L - 1);
    }
    __syncthreads();
    if (!is_last) return;

    __threadfence();
    __shared__ float sm[L];
    int t = threadIdx.x;
    float v = 0.f;
    if (t < L) { v = g_attn_scratch[t]; sm[t] = v; }
    __syncthreads();
    if (t < L) {
        for (int st = 64; st; st >>= 1) { if (t < st) sm[t] = fmaxf(sm[t], sm[t + st]); __syncthreads(); }
    } else { for (int st = 64; st; st >>= 1) __syncthreads(); }
    float m = sm[0]; __syncthreads();
    float e = (t < L) ? expf(v - m) : 0.f;
    if (t < L) sm[t] = e;
    __syncthreads();
    if (t < L) {
        for (int st = 64; st; st >>= 1) { if (t < st) sm[t] += sm[t + st]; __syncthreads(); }
    } else { for (int st = 64; st; st >>= 1) __syncthreads(); }
    if (t < L) {
        float wgt = e / sm[0];
        attn_w_out[t]     = wgt;
        g_attn_scratch[t] = wgt;
    }
    if (t == 0) g_ctr_attn = 0;
}

// ---------------------------------------------------------------------------
// attn_applied[j] = sum_l w[l] * enc[l][j]
// ---------------------------------------------------------------------------
__global__ void k_attn_applied(const float* __restrict__ enc) {
    int t  = threadIdx.x;
    int jl = t & 31, lg = t >> 5;
    int j  = blockIdx.x * 32 + jl;
    float acc = 0.f;
    #pragma unroll
    for (int k = 0; k < 16; k++) {
        int l = lg * 16 + k;
        acc += g_attn_scratch[l] * enc[l * H + j];
    }
    __shared__ float s[8][32];
    s[lg][jl] = acc;
    __syncthreads();
    if (lg == 0) {
        float v = acc;
        #pragma unroll
        for (int k = 1; k < 8; k++) v += s[k][jl];
        g_attn_applied[j] = v;
    }
}

// ---------------------------------------------------------------------------
// x = relu(comb_W @ [embedded||attn_applied] + comb_b), warp per row
// ---------------------------------------------------------------------------
__global__ void k_comb(const int* __restrict__ tokens,
                       const float* __restrict__ emb,
                       const float* __restrict__ comb_W,
                       const float* __restrict__ comb_b) {
    int warp = threadIdx.x >> 5, lane = threadIdx.x & 31;
    int row = blockIdx.x * 8 + warp;
    const float4* erow = (const float4*)(emb + (size_t)tokens[0] * H);
    const float4* arow = (const float4*)g_attn_applied;
    const float4* w    = (const float4*)(comb_W + (size_t)row * 2 * H);
    float4 wr[16];
    #pragma unroll
    for (int k = 0; k < 16; k++) wr[k] = __ldcs(w + lane + 32 * k);
    float acc = 0.f;
    #pragma unroll
    for (int k = 0; k < 16; k++) {
        int i = lane + 32 * k;
        float4 xv = (i < 256) ? erow[i] : arow[i - 256];
        acc += dot4(wr[k], xv);
    }
    acc = warp_sum(acc);
    if (lane == 0) g_x[row] = fmaxf(acc + comb_b[row], 0.f);
}

// ---------------------------------------------------------------------------
// k_ih: g_gates[r] += W_ih[r]·x (warp owns row r; k_hh stored base earlier).
// Last-arriving block runs the LSTM pointwise inline.
// ---------------------------------------------------------------------------
__global__ void __launch_bounds__(128) k_ih(const float* __restrict__ W_ih,
                                            const float* __restrict__ c0,
                                            float* __restrict__ h_out,
                                            float* __restrict__ c_out) {
    int tid = threadIdx.x, warp = tid >> 5, lane = tid & 31;
    int r = blockIdx.x * 4 + warp;
    const float4* w = (const float4*)(W_ih + (size_t)r * H);
    float4 vr[8];
    #pragma unroll
    for (int k = 0; k < 8; k++) vr[k] = __ldcs(w + lane + 32 * k);
    __shared__ float4 sx[256];
    sx[tid]       = ((const float4*)g_x)[tid];
    sx[tid + 128] = ((const float4*)g_x)[tid + 128];
    __syncthreads();
    float a = 0.f;
    #pragma unroll
    for (int k = 0; k < 8; k++) a += dot4(vr[k], sx[lane + 32 * k]);
    a = warp_sum(a);
    if (lane == 0) g_gates[r] += a;     // only owner warp touches row r

    __threadfence();
    __syncthreads();
    __shared__ unsigned s_last;
    if (tid == 0) s_last = (atomicAdd(&g_ctr_ih, 1u) == 1023u);
    __syncthreads();
    if (!s_last) return;

    // ---- fused LSTM pointwise ----
    __threadfence();
    for (int u = tid; u < H; u += 128) {
        float gi = g_gates[u], gf = g_gates[H + u];
        float gg = g_gates[2 * H + u], go = g_gates[3 * H + u];
        float ig = 1.f / (1.f + expf(-gi));
        float fg = 1.f / (1.f + expf(-gf));
        float gt = tanhf(gg);
        float og = 1.f / (1.f + expf(-go));
        float cn = fg * c0[u] + ig * gt;
        float hn = og * tanhf(cn);
        c_out[u] = cn; h_out[u] = hn; g_h[u] = hn;
    }
    if (tid == 0) g_ctr_ih = 0u;
}

// ---------------------------------------------------------------------------
// output projection: persistent 592 blocks, 3-stage bulk-copy pipeline (48KB
// dynamic smem), online logsumexp, fused logZ + final subtract (flag sync).
// ---------------------------------------------------------------------------
__global__ void __launch_bounds__(128, 4) k_out(const float* __restrict__ out_W,
                                                const float* __restrict__ out_b,
                                                float* __restrict__ out) {
    extern __shared__ __align__(128) char dsm[];
    float4*   buf  = (float4*)dsm;                          // 3 x 1024 float4 = 48KB
    float4*   sh4  = (float4*)(dsm + 3 * 16384);            // 256 float4 = 4KB
    uint64_t* mbarp = (uint64_t*)(dsm + 3 * 16384 + 4096);  // 3 barriers
    __shared__ float    s_red[8];
    __shared__ unsigned s_last;

    int tid = threadIdx.x, warp = tid >> 5, lane = tid & 31;
    int b = blockIdx.x;
    uint64_t pol = mkpolicy();
    unsigned mb[3] = { smem_u32(mbarp), smem_u32(mbarp + 1), smem_u32(mbarp + 2) };

    if (tid == 0) { mbar_init(mb[0], 1); mbar_init(mb[1], 1); mbar_init(mb[2], 1); }
    sh4[tid]       = ((const float4*)g_h)[tid];
    sh4[tid + 128] = ((const float4*)g_h)[tid + 128];
    __syncthreads();

    const int nt = 21 + (b < 132);                   // 12564 full 4-row tiles
    if (tid == 0) {
        #pragma unroll
        for (int k = 0; k < 3; k++) {
            mbar_expect(mb[k], TB);
            bulk_cp(buf + k * 1024, out_W + ((size_t)b + (size_t)NB * k) * 4 * H, TB, mb[k], pol);
        }
    }

    float m = -INFINITY, ss = 0.f;
    int s = 0;
    for (int k = 0; k < nt; k++) {
        mbar_wait(mb[s], (k / 3) & 1);
        size_t row = ((size_t)b + (size_t)NB * k) * 4 + warp;
        float a = 0.f;
        #pragma unroll
        for (int kk = 0; kk < 8; kk++)
            a += dot4(buf[s * 1024 + warp * 256 + lane + 32 * kk], sh4[lane + 32 * kk]);
        a = warp_sum(a);
        if (lane == 0) {
            float lg = a + out_b[row];
            out[row] = lg;
            if (lg > m) { ss = ss * expf(m - lg) + 1.f; m = lg; }
            else        { ss += expf(lg - m); }
        }
        __syncthreads();
        if (tid == 0 && k + 3 < nt) {
            mbar_expect(mb[s], TB);
            bulk_cp(buf + s * 1024, out_W + ((size_t)b + (size_t)NB * (k + 3)) * 4 * H, TB, mb[s], pol);
        }
        s = (s == 2) ? 0 : s + 1;
    }

    // tail row 50256 (block 0, warp 0)
    if (b == 0 && warp == 0) {
        const float4* w = (const float4*)(out_W + (size_t)50256 * H);
        float a = 0.f;
        #pragma unroll
        for (int kk = 0; kk < 8; kk++) a += dot4(__ldcs(w + lane + 32 * kk), sh4[lane + 32 * kk]);
        a = warp_sum(a);
        if (lane == 0) {
            float lg = a + out_b[50256];
            out[50256] = lg;
            if (lg > m) { ss = ss * expf(m - lg) + 1.f; m = lg; }
            else        { ss += expf(lg - m); }
        }
    }

    if (lane == 0) { s_red[warp] = m; s_red[4 + warp] = ss; }
    __syncthreads();
    if (tid == 0) {
        float M = fmaxf(fmaxf(s_red[0], s_red[1]), fmaxf(s_red[2], s_red[3]));
        float S = 0.f;
        #pragma unroll
        for (int k = 0; k < 4; k++) S += s_red[4 + k] * expf(s_red[k] - M);
        g_bmax[b] = M; g_bsum[b] = S;
        __threadfence();
        s_last = (atomicAdd(&g_ctr_out, 1u) == NB - 1);
    }
    __syncthreads();
    if (s_last) {
        __threadfence();
        float mm = -INFINITY;
        for (int k = tid; k < NB; k += 128) mm = fmaxf(mm, g_bmax[k]);
        mm = warp_max(mm);
        if (lane == 0) s_red[warp] = mm;
        __syncthreads();
        if (tid == 0) s_red[0] = fmaxf(fmaxf(s_red[0], s_red[1]), fmaxf(s_red[2], s_red[3]));
        __syncthreads();
        float M = s_red[0];
        __syncthreads();
        float S = 0.f;
        for (int k = tid; k < NB; k += 128) S += g_bsum[k] * expf(g_bmax[k] - M);
        S = warp_sum(S);
        if (lane == 0) s_red[4 + warp] = S;
        __syncthreads();
        if (tid == 0) {
            g_logZ = M + logf(s_red[4] + s_red[5] + s_red[6] + s_red[7]);
            g_ctr_out = 0u;
            __threadfence();
            atomicExch(&g_flag_z, 1u);
        }
    }

    if (tid == 0) { while (*(volatile unsigned*)&g_flag_z == 0u) __nanosleep(64); }
    __syncthreads(); __threadfence();
    float lz = g_logZ;
    for (int i = tid; i < nt * 4; i += 128) {
        size_t row = ((size_t)b + (size_t)NB * (i >> 2)) * 4 + (i & 3);
        out[row] -= lz;
    }
    if (b == 0 && tid == 0) out[50256] -= lz;
    __threadfence(); __syncthreads();
    if (tid == 0) {
        if (atomicAdd(&g_done, 1u) == NB - 1) { g_done = 0u; __threadfence(); atomicExch(&g_flag_z, 0u); }
    }
}

extern "C" void kernel_launch(void* const* d_in, const int* in_sizes, int n_in,
                              void* d_out, int out_size) {
    const int*   tokens = (const int*)  d_in[0];
    const float* h0     = (const float*)d_in[1];
    const float* c0     = (const float*)d_in[2];
    const float* enc    = (const float*)d_in[3];
    const float* emb    = (const float*)d_in[4];
    const float* attn_W = (const float*)d_in[5];
    const float* attn_b = (const float*)d_in[6];
    const float* comb_W = (const float*)d_in[7];
    const float* comb_b = (const float*)d_in[8];
    const float* W_ih   = (const float*)d_in[9];
    const float* W_hh   = (const float*)d_in[10];
    const float* b_ih   = (const float*)d_in[11];
    const float* b_hh   = (const float*)d_in[12];
    const float* out_W  = (const float*)d_in[13];
    const float* out_b  = (const float*)d_in[14];

    float* out    = (float*)d_out;          // [V] log-probs
    float* h_out  = out + V;                // [H]
    float* c_out  = out + V + H;            // [H]
    float* aw_out = out + V + 2 * H;        // [L]

    static int inited = 0;
    static cudaStream_t s2;
    static cudaEvent_t ev_fork, ev_join;
    const int OUT_SMEM = 3 * 16384 + 4096 + 32;
    if (!inited) {
        cudaFuncSetAttribute(k_out, cudaFuncAttributeMaxDynamicSharedMemorySize, OUT_SMEM);
        cudaStreamCreateWithFlags(&s2, cudaStreamNonBlocking);
        cudaEventCreateWithFlags(&ev_fork, cudaEventDisableTiming);
        cudaEventCreateWithFlags(&ev_join, cudaEventDisableTiming);
        inited = 1;
    }

    // fork: W_hh·h0 + biases runs concurrently with the attn chain
    cudaEventRecord(ev_fork, 0);
    cudaStreamWaitEvent(s2, ev_fork, 0);
    k_hh<<<H * 4 / 4, 128, 0, s2>>>(W_hh, h0, b_ih, b_hh);
    cudaEventRecord(ev_join, s2);

    k_attn        <<<L, 256>>>(tokens, emb, h0, attn_W, attn_b, aw_out);
    k_attn_applied<<<H / 32, 256>>>(enc);
    k_comb        <<<H / 8, 256>>>(tokens, emb, comb_W, comb_b);

    cudaStreamWaitEvent(0, ev_join, 0);
    k_ih          <<<H * 4 / 4, 128>>>(W_ih, c0, h_out, c_out);
    k_out         <<<NB, 128, OUT_SMEM>>>(out_W, out_b, out);
}

// round 12
// speedup vs baseline: 1.1318x; 1.0781x over previous
#include <cuda_runtime.h>
#include <math.h>
#include <stdint.h>

#define H 1024
#define V 50257
#define L 128
#define NB 592                  // 148 SMs x 4 resident
#define TB 16384u               // tile: 4 rows x 1024 floats

// ---- persistent scratch ----
__device__ __align__(16) float g_attn_scratch[L];
__device__ __align__(16) float g_attn_applied[H];
__device__ __align__(16) float g_x[H];
__device__ __align__(16) float g_h[H];
__device__ __align__(16) float g_gates[4 * H];   // preset with biases by k_comb
__device__ __align__(16) float g_bmax[NB];
__device__ __align__(16) float g_bsum[NB];
__device__ float    g_logZ;
__device__ unsigned g_ctr_attn = 0, g_ctr_out = 0, g_done = 0;
__device__ unsigned g_flag_z = 0;

__device__ __forceinline__ float warp_sum(float v) {
    #pragma unroll
    for (int o = 16; o; o >>= 1) v += __shfl_down_sync(0xffffffffu, v, o);
    return v;
}
__device__ __forceinline__ float warp_max(float v) {
    #pragma unroll
    for (int o = 16; o; o >>= 1) v = fmaxf(v, __shfl_down_sync(0xffffffffu, v, o));
    return v;
}
__device__ __forceinline__ float dot4(float4 a, float4 b) {
    return a.x * b.x + a.y * b.y + a.z * b.z + a.w * b.w;
}
__device__ __forceinline__ uint64_t mkpolicy() {
    uint64_t p;
    asm("createpolicy.fractional.L2::evict_first.b64 %0, 1.0;" : "=l"(p));
    return p;
}
__device__ __forceinline__ void bulk_cp(void* dst_smem, const void* src,
                                        unsigned bytes, unsigned mbar, uint64_t pol) {
    unsigned d = (unsigned)__cvta_generic_to_shared(dst_smem);
    asm volatile(
        "cp.async.bulk.shared::cluster.global.mbarrier::complete_tx::bytes.L2::cache_hint"
        " [%0], [%1], %2, [%3], %4;"
        :: "r"(d), "l"(src), "r"(bytes), "r"(mbar), "l"(pol) : "memory");
}
__device__ __forceinline__ void mbar_init(unsigned mbar, unsigned cnt) {
    asm volatile("mbarrier.init.shared.b64 [%0], %1;" :: "r"(mbar), "r"(cnt) : "memory");
}
__device__ __forceinline__ void mbar_expect(unsigned mbar, unsigned bytes) {
    asm volatile("mbarrier.arrive.expect_tx.shared.b64 _, [%0], %1;"
                 :: "r"(mbar), "r"(bytes) : "memory");
}
__device__ __forceinline__ void mbar_wait(unsigned mbar, unsigned parity) {
    asm volatile(
        "{\n\t.reg .pred P;\n\t"
        "W_%=:\n\t"
        "mbarrier.try_wait.parity.acquire.cta.shared::cta.b64 P, [%0], %1, 0x989680;\n\t"
        "@P bra.uni D_%=;\n\t"
        "bra.uni W_%=;\n\t"
        "D_%=:\n\t}"
        :: "r"(mbar), "r"(parity) : "memory");
}
__device__ __forceinline__ unsigned smem_u32(const void* p) {
    return (unsigned)__cvta_generic_to_shared(p);
}

// ---------------------------------------------------------------------------
// attn logits (block per row) + fused softmax in last arriving block
// ---------------------------------------------------------------------------
__global__ void k_attn(const int* __restrict__ tokens,
                       const float* __restrict__ emb,
                       const float* __restrict__ h0,
                       const float* __restrict__ attn_W,
                       const float* __restrict__ attn_b,
                       float* __restrict__ attn_w_out) {
    int l = blockIdx.x;
    const float4* erow = (const float4*)(emb + (size_t)tokens[0] * H);
    const float4* hrow = (const float4*)h0;
    const float4* w    = (const float4*)(attn_W + (size_t)l * 2 * H);
    float acc = 0.f;
    for (int i = threadIdx.x; i < 2 * H / 4; i += blockDim.x) {
        float4 wv = __ldcs(w + i);
        float4 xv = (i < H / 4) ? erow[i] : hrow[i - H / 4];
        acc += dot4(wv, xv);
    }
    __shared__ float s[8];
    acc = warp_sum(acc);
    if ((threadIdx.x & 31) == 0) s[threadIdx.x >> 5] = acc;
    __syncthreads();
    __shared__ unsigned is_last;
    if (threadIdx.x == 0) {
        float v = 0.f;
        #pragma unroll
        for (int k = 0; k < 8; k++) v += s[k];
        g_attn_scratch[l] = v + attn_b[l];
        __threadfence();
        is_last = (atomicAdd(&g_ctr_attn, 1u) == L - 1);
    }
    __syncthreads();
    if (!is_last) return;

    __threadfence();
    __shared__ float sm[L];
    int t = threadIdx.x;
    float v = 0.f;
    if (t < L) { v = g_attn_scratch[t]; sm[t] = v; }
    __syncthreads();
    if (t < L) {
        for (int st = 64; st; st >>= 1) { if (t < st) sm[t] = fmaxf(sm[t], sm[t + st]); __syncthreads(); }
    } else { for (int st = 64; st; st >>= 1) __syncthreads(); }
    float m = sm[0]; __syncthreads();
    float e = (t < L) ? expf(v - m) : 0.f;
    if (t < L) sm[t] = e;
    __syncthreads();
    if (t < L) {
        for (int st = 64; st; st >>= 1) { if (t < st) sm[t] += sm[t + st]; __syncthreads(); }
    } else { for (int st = 64; st; st >>= 1) __syncthreads(); }
    if (t < L) {
        float wgt = e / sm[0];
        attn_w_out[t]     = wgt;
        g_attn_scratch[t] = wgt;
    }
    if (t == 0) g_ctr_attn = 0;
}

// ---------------------------------------------------------------------------
// attn_applied[j] = sum_l w[l] * enc[l][j]
// ---------------------------------------------------------------------------
__global__ void k_attn_applied(const float* __restrict__ enc) {
    int t  = threadIdx.x;
    int jl = t & 31, lg = t >> 5;
    int j  = blockIdx.x * 32 + jl;
    float acc = 0.f;
    #pragma unroll
    for (int k = 0; k < 16; k++) {
        int l = lg * 16 + k;
        acc += g_attn_scratch[l] * enc[l * H + j];
    }
    __shared__ float s[8][32];
    s[lg][jl] = acc;
    __syncthreads();
    if (lg == 0) {
        float v = acc;
        #pragma unroll
        for (int k = 1; k < 8; k++) v += s[k][jl];
        g_attn_applied[j] = v;
    }
}

// ---------------------------------------------------------------------------
// x = relu(comb_W @ [embedded||attn_applied] + comb_b) + gate bias preset
// ---------------------------------------------------------------------------
__global__ void k_comb(const int* __restrict__ tokens,
                       const float* __restrict__ emb,
                       const float* __restrict__ comb_W,
                       const float* __restrict__ comb_b,
                       const float* __restrict__ b_ih,
                       const float* __restrict__ b_hh) {
    if (threadIdx.x < 32) {
        int gi = blockIdx.x * 32 + threadIdx.x;
        g_gates[gi] = b_ih[gi] + b_hh[gi];
    }
    int warp = threadIdx.x >> 5, lane = threadIdx.x & 31;
    int row = blockIdx.x * 8 + warp;
    const float4* erow = (const float4*)(emb + (size_t)tokens[0] * H);
    const float4* arow = (const float4*)g_attn_applied;
    const float4* w    = (const float4*)(comb_W + (size_t)row * 2 * H);
    float4 wr[16];
    #pragma unroll
    for (int k = 0; k < 16; k++) wr[k] = __ldcs(w + lane + 32 * k);
    float acc = 0.f;
    #pragma unroll
    for (int k = 0; k < 16; k++) {
        int i = lane + 32 * k;
        float4 xv = (i < 256) ? erow[i] : arow[i - 256];
        acc += dot4(wr[k], xv);
    }
    acc = warp_sum(acc);
    if (lane == 0) g_x[row] = fmaxf(acc + comb_b[row], 0.f);
}

// ---------------------------------------------------------------------------
// k_gates: persistent 592 blocks, 3-4 tiles each, double-buffered bulk copies.
// Tiles 0..1023 = W_ih (vs x); 1024..2047 = W_hh (vs h0).
// NO fence/counter in the loop — ordering to k_lstm_pw via kernel boundary.
// ---------------------------------------------------------------------------
__global__ void __launch_bounds__(128) k_gates(const float* __restrict__ W_ih,
                                               const float* __restrict__ W_hh,
                                               const float* __restrict__ h0) {
    __shared__ __align__(128) float4 buf[2][1024];   // 32KB
    __shared__ float4 svx[256], svh[256];
    __shared__ uint64_t mbar[2];
    int tid = threadIdx.x, warp = tid >> 5, lane = tid & 31;
    int b = blockIdx.x;
    uint64_t pol = mkpolicy();
    unsigned mb[2] = { smem_u32(&mbar[0]), smem_u32(&mbar[1]) };

    if (tid == 0) { mbar_init(mb[0], 1); mbar_init(mb[1], 1); }
    svx[tid]       = ((const float4*)g_x)[tid];
    svx[tid + 128] = ((const float4*)g_x)[tid + 128];
    svh[tid]       = ((const float4*)h0)[tid];
    svh[tid + 128] = ((const float4*)h0)[tid + 128];
    __syncthreads();

    int nt = (2048 - b + NB - 1) / NB;               // 4 for b<272, else 3
    if (tid == 0) {
        const float* s0 = (b < 1024) ? W_ih + (size_t)b * 4 * H
                                     : W_hh + (size_t)(b - 1024) * 4 * H;
        mbar_expect(mb[0], TB); bulk_cp(buf[0], s0, TB, mb[0], pol);
        int t1 = b + NB;
        const float* s1 = (t1 < 1024) ? W_ih + (size_t)t1 * 4 * H
                                      : W_hh + (size_t)(t1 - 1024) * 4 * H;
        mbar_expect(mb[1], TB); bulk_cp(buf[1], s1, TB, mb[1], pol);
    }

    for (int k = 0; k < nt; k++) {
        int s = k & 1;
        mbar_wait(mb[s], (k >> 1) & 1);
        int t = b + NB * k;
        const float4* vec = (t < 1024) ? svx : svh;
        float a = 0.f;
        #pragma unroll
        for (int kk = 0; kk < 8; kk++)
            a += dot4(buf[s][warp * 256 + lane + 32 * kk], vec[lane + 32 * kk]);
        a = warp_sum(a);
        if (lane == 0) atomicAdd(&g_gates[(4 * t + warp) & 4095], a);
        __syncthreads();                              // buf[s] fully consumed
        if (tid == 0 && k + 2 < nt) {
            int tn = b + NB * (k + 2);
            const float* sn = (tn < 1024) ? W_ih + (size_t)tn * 4 * H
                                          : W_hh + (size_t)(tn - 1024) * 4 * H;
            mbar_expect(mb[s], TB); bulk_cp(buf[s], sn, TB, mb[s], pol);
        }
    }
}

// ---------------------------------------------------------------------------
// LSTM pointwise: gates -> c_new, h_new
// ---------------------------------------------------------------------------
__global__ void k_lstm_pw(const float* __restrict__ c0,
                          float* __restrict__ h_out, float* __restrict__ c_out) {
    int j = blockIdx.x * 256 + threadIdx.x;
    float gi = g_gates[j], gf = g_gates[H + j], gg = g_gates[2 * H + j], go = g_gates[3 * H + j];
    float ig = 1.f / (1.f + expf(-gi));
    float fg = 1.f / (1.f + expf(-gf));
    float gt = tanhf(gg);
    float og = 1.f / (1.f + expf(-go));
    float cn = fg * c0[j] + ig * gt;
    float hn = og * tanhf(cn);
    c_out[j] = cn;
    h_out[j] = hn;
    g_h[j]   = hn;
}

// ---------------------------------------------------------------------------
// output projection: persistent 592 blocks, 3-stage bulk-copy pipeline (48KB
// dynamic smem), online logsumexp, fused logZ + final subtract (flag sync).
// ---------------------------------------------------------------------------
__global__ void __launch_bounds__(128, 4) k_out(const float* __restrict__ out_W,
                                                const float* __restrict__ out_b,
                                                float* __restrict__ out) {
    extern __shared__ __align__(128) char dsm[];
    float4*   buf  = (float4*)dsm;                          // 3 x 1024 float4 = 48KB
    float4*   sh4  = (float4*)(dsm + 3 * 16384);            // 256 float4 = 4KB
    uint64_t* mbarp = (uint64_t*)(dsm + 3 * 16384 + 4096);  // 3 barriers
    __shared__ float    s_red[8];
    __shared__ unsigned s_last;

    int tid = threadIdx.x, warp = tid >> 5, lane = tid & 31;
    int b = blockIdx.x;
    uint64_t pol = mkpolicy();
    unsigned mb[3] = { smem_u32(mbarp), smem_u32(mbarp + 1), smem_u32(mbarp + 2) };

    if (tid == 0) { mbar_init(mb[0], 1); mbar_init(mb[1], 1); mbar_init(mb[2], 1); }
    sh4[tid]       = ((const float4*)g_h)[tid];
    sh4[tid + 128] = ((const float4*)g_h)[tid + 128];
    __syncthreads();

    const int nt = 21 + (b < 132);                   // 12564 full 4-row tiles
    if (tid == 0) {
        #pragma unroll
        for (int k = 0; k < 3; k++) {
            mbar_expect(mb[k], TB);
            bulk_cp(buf + k * 1024, out_W + ((size_t)b + (size_t)NB * k) * 4 * H, TB, mb[k], pol);
        }
    }

    float m = -INFINITY, ss = 0.f;
    int s = 0;
    for (int k = 0; k < nt; k++) {
        mbar_wait(mb[s], (k / 3) & 1);
        size_t row = ((size_t)b + (size_t)NB * k) * 4 + warp;
        float a = 0.f;
        #pragma unroll
        for (int kk = 0; kk < 8; kk++)
            a += dot4(buf[s * 1024 + warp * 256 + lane + 32 * kk], sh4[lane + 32 * kk]);
        a = warp_sum(a);
        if (lane == 0) {
            float lg = a + out_b[row];
            out[row] = lg;
            if (lg > m) { ss = ss * expf(m - lg) + 1.f; m = lg; }
            else        { ss += expf(lg - m); }
        }
        __syncthreads();
        if (tid == 0 && k + 3 < nt) {
            mbar_expect(mb[s], TB);
            bulk_cp(buf + s * 1024, out_W + ((size_t)b + (size_t)NB * (k + 3)) * 4 * H, TB, mb[s], pol);
        }
        s = (s == 2) ? 0 : s + 1;
    }

    // tail row 50256 (block 0, warp 0)
    if (b == 0 && warp == 0) {
        const float4* w = (const float4*)(out_W + (size_t)50256 * H);
        float a = 0.f;
        #pragma unroll
        for (int kk = 0; kk < 8; kk++) a += dot4(__ldcs(w + lane + 32 * kk), sh4[lane + 32 * kk]);
        a = warp_sum(a);
        if (lane == 0) {
            float lg = a + out_b[50256];
            out[50256] = lg;
            if (lg > m) { ss = ss * expf(m - lg) + 1.f; m = lg; }
            else        { ss += expf(lg - m); }
        }
    }

    if (lane == 0) { s_red[warp] = m; s_red[4 + warp] = ss; }
    __syncthreads();
    if (tid == 0) {
        float M = fmaxf(fmaxf(s_red[0], s_red[1]), fmaxf(s_red[2], s_red[3]));
        float S = 0.f;
        #pragma unroll
        for (int k = 0; k < 4; k++) S += s_red[4 + k] * expf(s_red[k] - M);
        g_bmax[b] = M; g_bsum[b] = S;
        __threadfence();
        s_last = (atomicAdd(&g_ctr_out, 1u) == NB - 1);
    }
    __syncthreads();
    if (s_last) {
        __threadfence();
        float mm = -INFINITY;
        for (int k = tid; k < NB; k += 128) mm = fmaxf(mm, g_bmax[k]);
        mm = warp_max(mm);
        if (lane == 0) s_red[warp] = mm;
        __syncthreads();
        if (tid == 0) s_red[0] = fmaxf(fmaxf(s_red[0], s_red[1]), fmaxf(s_red[2], s_red[3]));
        __syncthreads();
        float M = s_red[0];
        __syncthreads();
        float S = 0.f;
        for (int k = tid; k < NB; k += 128) S += g_bsum[k] * expf(g_bmax[k] - M);
        S = warp_sum(S);
        if (lane == 0) s_red[4 + warp] = S;
        __syncthreads();
        if (tid == 0) {
            g_logZ = M + logf(s_red[4] + s_red[5] + s_red[6] + s_red[7]);
            g_ctr_out = 0u;
            __threadfence();
            atomicExch(&g_flag_z, 1u);
        }
    }

    if (tid == 0) { while (*(volatile unsigned*)&g_flag_z == 0u) __nanosleep(64); }
    __syncthreads(); __threadfence();
    float lz = g_logZ;
    for (int i = tid; i < nt * 4; i += 128) {
        size_t row = ((size_t)b + (size_t)NB * (i >> 2)) * 4 + (i & 3);
        out[row] -= lz;
    }
    if (b == 0 && tid == 0) out[50256] -= lz;
    __threadfence(); __syncthreads();
    if (tid == 0) {
        if (atomicAdd(&g_done, 1u) == NB - 1) { g_done = 0u; __threadfence(); atomicExch(&g_flag_z, 0u); }
    }
}

extern "C" void kernel_launch(void* const* d_in, const int* in_sizes, int n_in,
                              void* d_out, int out_size) {
    const int*   tokens = (const int*)  d_in[0];
    const float* h0     = (const float*)d_in[1];
    const float* c0     = (const float*)d_in[2];
    const float* enc    = (const float*)d_in[3];
    const float* emb    = (const float*)d_in[4];
    const float* attn_W = (const float*)d_in[5];
    const float* attn_b = (const float*)d_in[6];
    const float* comb_W = (const float*)d_in[7];
    const float* comb_b = (const float*)d_in[8];
    const float* W_ih   = (const float*)d_in[9];
    const float* W_hh   = (const float*)d_in[10];
    const float* b_ih   = (const float*)d_in[11];
    const float* b_hh   = (const float*)d_in[12];
    const float* out_W  = (const float*)d_in[13];
    const float* out_b  = (const float*)d_in[14];

    float* out    = (float*)d_out;          // [V] log-probs
    float* h_out  = out + V;                // [H]
    float* c_out  = out + V + H;            // [H]
    float* aw_out = out + V + 2 * H;        // [L]

    static int inited = 0;
    const int OUT_SMEM = 3 * 16384 + 4096 + 32;
    if (!inited) {
        cudaFuncSetAttribute(k_out, cudaFuncAttributeMaxDynamicSharedMemorySize, OUT_SMEM);
        inited = 1;
    }

    k_attn        <<<L, 256>>>(tokens, emb, h0, attn_W, attn_b, aw_out);
    k_attn_applied<<<H / 32, 256>>>(enc);
    k_comb        <<<H / 8, 256>>>(tokens, emb, comb_W, comb_b, b_ih, b_hh);
    k_gates       <<<NB, 128>>>(W_ih, W_hh, h0);
    k_lstm_pw     <<<H / 256, 256>>>(c0, h_out, c_out);
    k_out         <<<NB, 128, OUT_SMEM>>>(out_W, out_b, out);
}